// round 14
// baseline (speedup 1.0000x reference)
#include <cuda_runtime.h>
#include <math.h>

#define BATCH 2
#define SEQ   1024
#define DIMC  256
#define HEADS 4
#define DH    64
#define INNER 256
#define MTOK  (BATCH*SEQ)   // 2048
#define DEPTH 4

#define ACT_CAP ((size_t)MTOK*DIMC)                 // 524288
#define SCR_CAP ((size_t)BATCH*HEADS*SEQ*SEQ)       // 8388608
#define NROWS   (BATCH*HEADS*SEQ)                   // 8192

#define BK 16
#define BKG 32     // K-slice for dense GEMMs
#define BPAD 68

// ---------------- scratch (device globals) ----------------
__device__ float g_x_re[ACT_CAP],  g_x_im[ACT_CAP];
__device__ float g_xn_re[ACT_CAP], g_xn_im[ACT_CAP];
__device__ float g_w_re[ACT_CAP],  g_w_im[ACT_CAP];
__device__ float g_att_re[ACT_CAP],g_att_im[ACT_CAP];
__device__ float g_gx_re[ACT_CAP], g_gx_im[ACT_CAP];
__device__ float g_d_re[SCR_CAP];   // unit phase re (from dots)
__device__ float g_d_im[SCR_CAP];   // unit phase im
__device__ float g_d_mg[SCR_CAP];   // scaled magnitude
__device__ float g_row_max[NROWS];  // per-score-row max of mg
__device__ float g_row_inv[NROWS];  // per-score-row 1/sum(exp(mg-max))

__device__ __forceinline__ float* gbuf(int id, int comp) {
    switch (id) {
        case 0: return comp ? g_x_im   : g_x_re;
        case 1: return comp ? g_xn_im  : g_xn_re;
        case 2: return comp ? g_w_im   : g_w_re;
        case 3: return comp ? g_att_im : g_att_re;
        default:return comp ? g_gx_im  : g_gx_re;
    }
}

// ---------------- input copy ----------------
__global__ void init_x_kernel(const float* __restrict__ a, const float* __restrict__ b, int n)
{
    int i = blockIdx.x*blockDim.x + threadIdx.x;
    if (i < n) { g_x_re[i] = a[i]; g_x_im[i] = b[i]; }
}

// ---------------- output pack: real part only ----------------
__global__ void pack_out_kernel(float* __restrict__ out, int n)
{
    int i = blockIdx.x*blockDim.x + threadIdx.x;
    if (i < n) out[i] = g_x_re[i];
}

// ---------------- complex layernorm ----------------
__global__ void ln_kernel(int srcid,
                          const float* __restrict__ wr, const float* __restrict__ wi,
                          const float* __restrict__ br, const float* __restrict__ bi)
{
    const float* xr = gbuf(srcid, 0);
    const float* xi = gbuf(srcid, 1);
    float* yr = gbuf(1, 0);
    float* yi = gbuf(1, 1);

    int tok = blockIdx.x;
    int t   = threadIdx.x;
    size_t xidx = (size_t)tok*DIMC + t;
    float vr = xr[xidx];
    float vi = xi[xidx];

    float s0 = vr, s1 = vi, s2 = vr*vr, s3 = vi*vi;
    #pragma unroll
    for (int o = 16; o > 0; o >>= 1) {
        s0 += __shfl_xor_sync(0xffffffffu, s0, o);
        s1 += __shfl_xor_sync(0xffffffffu, s1, o);
        s2 += __shfl_xor_sync(0xffffffffu, s2, o);
        s3 += __shfl_xor_sync(0xffffffffu, s3, o);
    }
    __shared__ float sh0[8], sh1[8], sh2[8], sh3[8];
    int warp = t >> 5;
    if ((t & 31) == 0) { sh0[warp]=s0; sh1[warp]=s1; sh2[warp]=s2; sh3[warp]=s3; }
    __syncthreads();
    float t0=0.f, t1=0.f, t2=0.f, t3=0.f;
    #pragma unroll
    for (int i = 0; i < 8; i++) { t0+=sh0[i]; t1+=sh1[i]; t2+=sh2[i]; t3+=sh3[i]; }

    const float inv = 1.0f / DIMC;
    float mr = t0*inv, mi = t1*inv;
    float var_r = t2*inv - mr*mr;
    float var_i = t3*inv - mi*mi;
    float a = var_r + 1e-5f, b = var_i;
    float r = sqrtf(a*a + b*b);
    float sre = sqrtf(fmaxf(0.5f*(r + a), 0.f));
    float sim = sqrtf(fmaxf(0.5f*(r - a), 0.f));
    if (b < 0.f) sim = -sim;
    float invr = 1.0f / fmaxf(r, 1e-30f);
    float dxr = vr - mr, dxi = vi - mi;
    float xnr = (dxr*sre + dxi*sim) * invr;
    float xni = (dxi*sre - dxr*sim) * invr;
    float Wr = wr[t], Wi = wi[t];
    yr[xidx] = Wr*xnr - Wi*xni + br[t];
    yi[xidx] = Wr*xni + Wi*xnr + bi[t];
}

#define LOAD_FRAG(dst, arr, kk, off)  { float4 _f = *(const float4*)&arr[kk][off]; \
                                        dst[0]=_f.x; dst[1]=_f.y; dst[2]=_f.z; dst[3]=_f.w; }

// ---------------- complex GEMM: Y[M,N] = X[M,K] @ W[N,K]^T (+ epilogue), BK=32 ----------------
template <int MODE>
__global__ __launch_bounds__(256, 2)
void gemm_xwt(int xid,
              const float* __restrict__ Wr, const float* __restrict__ Wi,
              int yid, int K, int ldx, int ldw, int ldy,
              const float* __restrict__ br, const float* __restrict__ bi,
              int rid)
{
    const float* Xr = gbuf(xid, 0);
    const float* Xi = gbuf(xid, 1);
    float* Yr = gbuf(yid, 0);
    float* Yi = gbuf(yid, 1);

    __shared__ __align__(16) float As_r[BKG][BPAD], As_i[BKG][BPAD];
    __shared__ __align__(16) float Bs_r[BKG][BPAD], Bs_i[BKG][BPAD];

    int tid = threadIdx.x;
    int tx = tid & 15, ty = tid >> 4;
    int row0 = blockIdx.y*64, col0 = blockIdx.x*64;

    float cr[4][4] = {}, ci[4][4] = {};

    for (int kt = 0; kt < K; kt += BKG) {
        #pragma unroll
        for (int i = 0; i < 8; i++) {
            int e = tid + i*256;
            int r = e >> 5, c = e & 31;      // 64 rows x 32 k
            As_r[c][r] = Xr[(size_t)(row0+r)*ldx + kt + c];
            As_i[c][r] = Xi[(size_t)(row0+r)*ldx + kt + c];
            Bs_r[c][r] = Wr[(size_t)(col0+r)*ldw + kt + c];
            Bs_i[c][r] = Wi[(size_t)(col0+r)*ldw + kt + c];
        }
        __syncthreads();
        #pragma unroll
        for (int kk = 0; kk < BKG; kk++) {
            float ar[4], ai_[4], br_[4], bi_[4];
            LOAD_FRAG(ar,  As_r, kk, ty*4);
            LOAD_FRAG(ai_, As_i, kk, ty*4);
            LOAD_FRAG(br_, Bs_r, kk, tx*4);
            LOAD_FRAG(bi_, Bs_i, kk, tx*4);
            #pragma unroll
            for (int i = 0; i < 4; i++)
                #pragma unroll
                for (int j = 0; j < 4; j++) {
                    cr[i][j] += ar[i]*br_[j] - ai_[i]*bi_[j];
                    ci[i][j] += ar[i]*bi_[j] + ai_[i]*br_[j];
                }
        }
        __syncthreads();
    }

    const float* rr = gbuf(rid, 0);
    const float* ri = gbuf(rid, 1);
    int colb = col0 + tx*4;
    #pragma unroll
    for (int i = 0; i < 4; i++) {
        int row = row0 + ty*4 + i;
        size_t oi = (size_t)row*ldy + colb;
        float4 yr4, yi4;
        if (MODE == 0) {
            yr4 = make_float4(cr[i][0], cr[i][1], cr[i][2], cr[i][3]);
            yi4 = make_float4(ci[i][0], ci[i][1], ci[i][2], ci[i][3]);
        } else if (MODE == 1) {
            float4 b_r = *(const float4*)&br[colb];
            float4 b_i = *(const float4*)&bi[colb];
            float4 r_r = *(const float4*)&rr[oi];
            float4 r_i = *(const float4*)&ri[oi];
            yr4 = make_float4(cr[i][0]+b_r.x+r_r.x, cr[i][1]+b_r.y+r_r.y,
                              cr[i][2]+b_r.z+r_r.z, cr[i][3]+b_r.w+r_r.w);
            yi4 = make_float4(ci[i][0]+b_i.x+r_i.x, ci[i][1]+b_i.y+r_i.y,
                              ci[i][2]+b_i.z+r_i.z, ci[i][3]+b_i.w+r_i.w);
        } else {
            float4 r_r = *(const float4*)&rr[oi];
            float4 r_i = *(const float4*)&ri[oi];
            yr4 = make_float4(fmaxf(r_r.x + 0.1f*cr[i][0] - 0.01f, 0.f),
                              fmaxf(r_r.y + 0.1f*cr[i][1] - 0.01f, 0.f),
                              fmaxf(r_r.z + 0.1f*cr[i][2] - 0.01f, 0.f),
                              fmaxf(r_r.w + 0.1f*cr[i][3] - 0.01f, 0.f));
            yi4 = make_float4(fmaxf(r_i.x + 0.1f*ci[i][0], 0.f),
                              fmaxf(r_i.y + 0.1f*ci[i][1], 0.f),
                              fmaxf(r_i.z + 0.1f*ci[i][2], 0.f),
                              fmaxf(r_i.w + 0.1f*ci[i][3], 0.f));
        }
        *(float4*)&Yr[oi] = yr4;
        *(float4*)&Yi[oi] = yi4;
    }
}

// ---------------- dots: Hermitian upper-triangle, scalar FFMA, phase+magnitude epilogue ------
__global__ __launch_bounds__(256, 2)
void dots_kernel()
{
    int bh = blockIdx.y;
    int b = bh >> 2, h = bh & 3;
    const float* Ar = g_w_re + (size_t)b*SEQ*INNER + h*DH;
    const float* Ai = g_w_im + (size_t)b*SEQ*INNER + h*DH;

    int t = blockIdx.x, bi = 0;
    while (t >= 16 - bi) { t -= 16 - bi; bi++; }
    int bj = bi + t;
    int row0 = bi*64, col0 = bj*64;

    __shared__ __align__(16) float As_r[BK][BPAD], As_i[BK][BPAD];
    __shared__ __align__(16) float Bs_r[BK][BPAD], Bs_i[BK][BPAD];

    int tid = threadIdx.x;
    int tx = tid & 15, ty = tid >> 4;

    float cr[4][4] = {}, ci[4][4] = {};

    #pragma unroll
    for (int kt = 0; kt < DH; kt += BK) {
        #pragma unroll
        for (int i = 0; i < 4; i++) {
            int e = tid + i*256;
            int r = e >> 4, c = e & 15;
            As_r[c][r] = Ar[(size_t)(row0+r)*INNER + kt + c];
            As_i[c][r] = Ai[(size_t)(row0+r)*INNER + kt + c];
            Bs_r[c][r] = Ar[(size_t)(col0+r)*INNER + kt + c];
            Bs_i[c][r] = Ai[(size_t)(col0+r)*INNER + kt + c];
        }
        __syncthreads();
        #pragma unroll
        for (int kk = 0; kk < BK; kk++) {
            float qr[4], qi[4], kr[4], ki[4];
            LOAD_FRAG(qr, As_r, kk, ty*4);
            LOAD_FRAG(qi, As_i, kk, ty*4);
            LOAD_FRAG(kr, Bs_r, kk, tx*4);
            LOAD_FRAG(ki, Bs_i, kk, tx*4);
            #pragma unroll
            for (int i = 0; i < 4; i++)
                #pragma unroll
                for (int j = 0; j < 4; j++) {
                    cr[i][j] += qr[i]*kr[j] + qi[i]*ki[j];
                    ci[i][j] += qi[i]*kr[j] - qr[i]*ki[j];
                }
        }
        __syncthreads();
    }

    const float SCALE = 0.125f;
    size_t obase = (size_t)bh*SEQ*SEQ;

    float ur[4][4], ui[4][4], mg[4][4];
    #pragma unroll
    for (int i = 0; i < 4; i++)
        #pragma unroll
        for (int j = 0; j < 4; j++) {
            float d2 = cr[i][j]*cr[i][j] + ci[i][j]*ci[i][j];
            float rs = rsqrtf(d2);
            bool  nz = d2 > 0.f;
            mg[i][j] = nz ? SCALE*d2*rs : 0.f;
            ur[i][j] = nz ? cr[i][j]*rs : 1.f;
            ui[i][j] = nz ? ci[i][j]*rs : 0.f;
        }

    int colb = col0 + tx*4;
    #pragma unroll
    for (int i = 0; i < 4; i++) {
        int row = row0 + ty*4 + i;
        size_t oi = obase + (size_t)row*SEQ + colb;
        *(float4*)&g_d_re[oi] = make_float4(ur[i][0], ur[i][1], ur[i][2], ur[i][3]);
        *(float4*)&g_d_im[oi] = make_float4(ui[i][0], ui[i][1], ui[i][2], ui[i][3]);
        *(float4*)&g_d_mg[oi] = make_float4(mg[i][0], mg[i][1], mg[i][2], mg[i][3]);
    }

    if (bi != bj) {
        int rowt = row0 + ty*4;
        #pragma unroll
        for (int j = 0; j < 4; j++) {
            int rt = colb + j;
            size_t oi = obase + (size_t)rt*SEQ + rowt;
            *(float4*)&g_d_re[oi] = make_float4( ur[0][j],  ur[1][j],  ur[2][j],  ur[3][j]);
            *(float4*)&g_d_im[oi] = make_float4(-ui[0][j], -ui[1][j], -ui[2][j], -ui[3][j]);
            *(float4*)&g_d_mg[oi] = make_float4( mg[0][j],  mg[1][j],  mg[2][j],  mg[3][j]);
        }
    }
}

// ---------------- softmax stats: per row max & 1/sum(exp(mg-max)) ----------------
__global__ void softmax_stats()
{
    size_t base = (size_t)blockIdx.x * SEQ;
    int t = threadIdx.x;
    float mg[4];
    float lmax = -3.4e38f;
    #pragma unroll
    for (int j = 0; j < 4; j++) {
        mg[j] = g_d_mg[base + t + 256*j];
        lmax = fmaxf(lmax, mg[j]);
    }
    __shared__ float sw[8];
    float v = lmax;
    #pragma unroll
    for (int o = 16; o > 0; o >>= 1) v = fmaxf(v, __shfl_xor_sync(0xffffffffu, v, o));
    if ((t & 31) == 0) sw[t>>5] = v;
    __syncthreads();
    float bmax = fmaxf(fmaxf(fmaxf(sw[0],sw[1]),fmaxf(sw[2],sw[3])),
                       fmaxf(fmaxf(sw[4],sw[5]),fmaxf(sw[6],sw[7])));
    __syncthreads();

    float lsum = 0.f;
    #pragma unroll
    for (int j = 0; j < 4; j++) lsum += __expf(mg[j] - bmax);
    v = lsum;
    #pragma unroll
    for (int o = 16; o > 0; o >>= 1) v += __shfl_xor_sync(0xffffffffu, v, o);
    if ((t & 31) == 0) sw[t>>5] = v;
    __syncthreads();
    float bsum = sw[0]+sw[1]+sw[2]+sw[3]+sw[4]+sw[5]+sw[6]+sw[7];

    if (t == 0) {
        g_row_max[blockIdx.x] = bmax;
        g_row_inv[blockIdx.x] = 1.0f / bsum;
    }
}

// ---------------- AV with fused softmax: coef = exp(mg-max)*inv * phase ----------------
__global__ __launch_bounds__(256, 2)
void av_kernel()
{
    int bh = blockIdx.y; int b = bh >> 2, h = bh & 3;
    const float* Cr = g_d_re + (size_t)bh*SEQ*SEQ;
    const float* Ci = g_d_im + (size_t)bh*SEQ*SEQ;
    const float* Cm = g_d_mg + (size_t)bh*SEQ*SEQ;
    const float* Vr = g_w_re + (size_t)b*SEQ*INNER + h*DH;
    const float* Vi = g_w_im + (size_t)b*SEQ*INNER + h*DH;

    __shared__ __align__(16) float As_r[BK][36], As_i[BK][36];
    __shared__ __align__(16) float Bs_r[BK][BPAD], Bs_i[BK][BPAD];
    __shared__ float s_max[32], s_inv[32];

    int tid = threadIdx.x;
    int tx = tid & 15, ty = tid >> 4;
    int row0 = blockIdx.x*32;

    if (tid < 32) {
        int rowi = bh*SEQ + row0 + tid;
        s_max[tid] = g_row_max[rowi];
        s_inv[tid] = g_row_inv[rowi];
    }
    __syncthreads();

    float cr[2][4] = {}, ci[2][4] = {};

    for (int kt = 0; kt < SEQ; kt += BK) {
        #pragma unroll
        for (int i = 0; i < 2; i++) {
            int e = tid + i*256;
            int r = e >> 4, c = e & 15;
            size_t si = (size_t)(row0+r)*SEQ + kt + c;
            float amp = __expf(Cm[si] - s_max[r]) * s_inv[r];
            As_r[c][r] = Cr[si] * amp;
            As_i[c][r] = Ci[si] * amp;
        }
        #pragma unroll
        for (int i = 0; i < 4; i++) {
            int e = tid + i*256;
            int r = e >> 6, c = e & 63;
            Bs_r[r][c] = Vr[(size_t)(kt+r)*INNER + c];
            Bs_i[r][c] = Vi[(size_t)(kt+r)*INNER + c];
        }
        __syncthreads();
        #pragma unroll
        for (int kk = 0; kk < BK; kk++) {
            float2 arf = *(const float2*)&As_r[kk][ty*2];
            float2 aif = *(const float2*)&As_i[kk][ty*2];
            float br_[4], bi_[4];
            LOAD_FRAG(br_, Bs_r, kk, tx*4);
            LOAD_FRAG(bi_, Bs_i, kk, tx*4);
            float ar[2]  = {arf.x, arf.y};
            float ai_[2] = {aif.x, aif.y};
            #pragma unroll
            for (int i = 0; i < 2; i++)
                #pragma unroll
                for (int j = 0; j < 4; j++) {
                    cr[i][j] += ar[i]*br_[j] - ai_[i]*bi_[j];
                    ci[i][j] += ar[i]*bi_[j] + ai_[i]*br_[j];
                }
        }
        __syncthreads();
    }

    int colb = h*DH + tx*4;
    #pragma unroll
    for (int i = 0; i < 2; i++) {
        int row = row0 + ty*2 + i;
        size_t oi = (size_t)(b*SEQ + row)*INNER + colb;
        *(float4*)&g_att_re[oi] = make_float4(cr[i][0], cr[i][1], cr[i][2], cr[i][3]);
        *(float4*)&g_att_im[oi] = make_float4(ci[i][0], ci[i][1], ci[i][2], ci[i][3]);
    }
}

// ---------------- host launcher ----------------
extern "C" void kernel_launch(void* const* d_in, const int* in_sizes, int n_in,
                              void* d_out, int out_size)
{
    if (n_in < 18 || d_out == nullptr) return;

    int ix[2], nx = 0;
    int iw[6], nw = 0;
    int ip[10], np = 0;
    for (int i = 0; i < n_in; i++) {
        if      (in_sizes[i] == MTOK*DIMC        && nx < 2)  ix[nx++] = i;
        else if (in_sizes[i] == DEPTH*INNER*DIMC && nw < 6)  iw[nw++] = i;
        else if (in_sizes[i] == DEPTH*DIMC       && np < 10) ip[np++] = i;
    }
    if (nx != 2 || nw != 6 || np != 10) return;

    const float* x_re     = (const float*)d_in[ix[0]];
    const float* x_im     = (const float*)d_in[ix[1]];
    const float* qkv_re   = (const float*)d_in[iw[0]];
    const float* qkv_im   = (const float*)d_in[iw[1]];
    const float* out_w_re = (const float*)d_in[iw[2]];
    const float* out_w_im = (const float*)d_in[iw[3]];
    const float* ff_re    = (const float*)d_in[iw[4]];
    const float* ff_im    = (const float*)d_in[iw[5]];
    const float* ln1_w_re = (const float*)d_in[ip[0]];
    const float* ln1_w_im = (const float*)d_in[ip[1]];
    const float* ln1_b_re = (const float*)d_in[ip[2]];
    const float* ln1_b_im = (const float*)d_in[ip[3]];
    const float* out_b_re = (const float*)d_in[ip[4]];
    const float* out_b_im = (const float*)d_in[ip[5]];
    const float* ln2_w_re = (const float*)d_in[ip[6]];
    const float* ln2_w_im = (const float*)d_in[ip[7]];
    const float* ln2_b_re = (const float*)d_in[ip[8]];
    const float* ln2_b_im = (const float*)d_in[ip[9]];

    const int nTok = MTOK*DIMC;
    init_x_kernel<<<(nTok+255)/256, 256>>>(x_re, x_im, nTok);

    const int WSLICE = INNER*DIMC;
    for (int l = 0; l < DEPTH; l++) {
        ln_kernel<<<MTOK, 256>>>(0,
                                 ln1_w_re + l*DIMC, ln1_w_im + l*DIMC,
                                 ln1_b_re + l*DIMC, ln1_b_im + l*DIMC);
        gemm_xwt<0><<<dim3(INNER/64, MTOK/64), 256>>>(
            1, qkv_re + (size_t)l*WSLICE, qkv_im + (size_t)l*WSLICE,
            2, DIMC, DIMC, DIMC, INNER, nullptr, nullptr, 0);
        dots_kernel<<<dim3(136, BATCH*HEADS), 256>>>();
        softmax_stats<<<NROWS, 256>>>();
        av_kernel<<<dim3(SEQ/32, BATCH*HEADS), 256>>>();
        gemm_xwt<1><<<dim3(DIMC/64, MTOK/64), 256>>>(
            3, out_w_re + (size_t)l*WSLICE, out_w_im + (size_t)l*WSLICE,
            4, INNER, INNER, INNER, DIMC,
            out_b_re + l*DIMC, out_b_im + l*DIMC, 0);
        ln_kernel<<<MTOK, 256>>>(4,
                                 ln2_w_re + l*DIMC, ln2_w_im + l*DIMC,
                                 ln2_b_re + l*DIMC, ln2_b_im + l*DIMC);
        gemm_xwt<2><<<dim3(DIMC/64, MTOK/64), 256>>>(
            1, ff_re + (size_t)l*WSLICE, ff_im + (size_t)l*WSLICE,
            0, DIMC, DIMC, DIMC, DIMC,
            nullptr, nullptr, 1);
    }

    int nOut = nTok < out_size ? nTok : out_size;
    pack_out_kernel<<<(nOut+255)/256, 256>>>((float*)d_out, nOut);
}

// round 15
// speedup vs baseline: 1.1157x; 1.1157x over previous
#include <cuda_runtime.h>
#include <math.h>

#define BATCH 2
#define SEQ   1024
#define DIMC  256
#define HEADS 4
#define DH    64
#define INNER 256
#define MTOK  (BATCH*SEQ)   // 2048
#define DEPTH 4

#define ACT_CAP ((size_t)MTOK*DIMC)                 // 524288
#define SCR_CAP ((size_t)BATCH*HEADS*SEQ*SEQ)       // 8388608

#define BK 16
#define BPAD 68

// ---------------- cp.async helpers ----------------
__device__ __forceinline__ unsigned scvt(const void* p) {
    return (unsigned)__cvta_generic_to_shared(p);
}
#define CPA4(dst, src)  asm volatile("cp.async.ca.shared.global [%0], [%1], 4;"  :: "r"(dst), "l"(src) : "memory")
#define CPA16(dst, src) asm volatile("cp.async.ca.shared.global [%0], [%1], 16;" :: "r"(dst), "l"(src) : "memory")
#define CPCOMMIT() asm volatile("cp.async.commit_group;" ::: "memory")
#define CPWAIT0()  asm volatile("cp.async.wait_group 0;" ::: "memory")
#define CPWAIT1()  asm volatile("cp.async.wait_group 1;" ::: "memory")

// ---------------- scratch (device globals) ----------------
__device__ float g_x_re[ACT_CAP],  g_x_im[ACT_CAP];
__device__ float g_xn_re[ACT_CAP], g_xn_im[ACT_CAP];
__device__ float g_w_re[ACT_CAP],  g_w_im[ACT_CAP];
__device__ float g_att_re[ACT_CAP],g_att_im[ACT_CAP];
__device__ float g_gx_re[ACT_CAP], g_gx_im[ACT_CAP];
__device__ float g_d_re[SCR_CAP];   // unit phase re -> scaled coef re after softmax
__device__ float g_d_im[SCR_CAP];   // unit phase im -> scaled coef im after softmax
__device__ float g_d_mg[SCR_CAP];   // scaled magnitude

__device__ __forceinline__ float* gbuf(int id, int comp) {
    switch (id) {
        case 0: return comp ? g_x_im   : g_x_re;
        case 1: return comp ? g_xn_im  : g_xn_re;
        case 2: return comp ? g_w_im   : g_w_re;
        case 3: return comp ? g_att_im : g_att_re;
        default:return comp ? g_gx_im  : g_gx_re;
    }
}

// ---------------- input copy ----------------
__global__ void init_x_kernel(const float* __restrict__ a, const float* __restrict__ b, int n)
{
    int i = blockIdx.x*blockDim.x + threadIdx.x;
    if (i < n) { g_x_re[i] = a[i]; g_x_im[i] = b[i]; }
}

// ---------------- output pack: real part only ----------------
__global__ void pack_out_kernel(float* __restrict__ out, int n)
{
    int i = blockIdx.x*blockDim.x + threadIdx.x;
    if (i < n) out[i] = g_x_re[i];
}

// ---------------- complex layernorm ----------------
__global__ void ln_kernel(int srcid,
                          const float* __restrict__ wr, const float* __restrict__ wi,
                          const float* __restrict__ br, const float* __restrict__ bi)
{
    const float* xr = gbuf(srcid, 0);
    const float* xi = gbuf(srcid, 1);
    float* yr = gbuf(1, 0);
    float* yi = gbuf(1, 1);

    int tok = blockIdx.x;
    int t   = threadIdx.x;
    size_t xidx = (size_t)tok*DIMC + t;
    float vr = xr[xidx];
    float vi = xi[xidx];

    float s0 = vr, s1 = vi, s2 = vr*vr, s3 = vi*vi;
    #pragma unroll
    for (int o = 16; o > 0; o >>= 1) {
        s0 += __shfl_xor_sync(0xffffffffu, s0, o);
        s1 += __shfl_xor_sync(0xffffffffu, s1, o);
        s2 += __shfl_xor_sync(0xffffffffu, s2, o);
        s3 += __shfl_xor_sync(0xffffffffu, s3, o);
    }
    __shared__ float sh0[8], sh1[8], sh2[8], sh3[8];
    int warp = t >> 5;
    if ((t & 31) == 0) { sh0[warp]=s0; sh1[warp]=s1; sh2[warp]=s2; sh3[warp]=s3; }
    __syncthreads();
    float t0=0.f, t1=0.f, t2=0.f, t3=0.f;
    #pragma unroll
    for (int i = 0; i < 8; i++) { t0+=sh0[i]; t1+=sh1[i]; t2+=sh2[i]; t3+=sh3[i]; }

    const float inv = 1.0f / DIMC;
    float mr = t0*inv, mi = t1*inv;
    float var_r = t2*inv - mr*mr;
    float var_i = t3*inv - mi*mi;
    float a = var_r + 1e-5f, b = var_i;
    float r = sqrtf(a*a + b*b);
    float sre = sqrtf(fmaxf(0.5f*(r + a), 0.f));
    float sim = sqrtf(fmaxf(0.5f*(r - a), 0.f));
    if (b < 0.f) sim = -sim;
    float invr = 1.0f / fmaxf(r, 1e-30f);
    float dxr = vr - mr, dxi = vi - mi;
    float xnr = (dxr*sre + dxi*sim) * invr;
    float xni = (dxi*sre - dxr*sim) * invr;
    float Wr = wr[t], Wi = wi[t];
    yr[xidx] = Wr*xnr - Wi*xni + br[t];
    yi[xidx] = Wr*xni + Wi*xnr + bi[t];
}

#define LOAD_FRAG(dst, arr, kk, off)  { float4 _f = *(const float4*)&arr[kk][off]; \
                                        dst[0]=_f.x; dst[1]=_f.y; dst[2]=_f.z; dst[3]=_f.w; }

// ---------------- complex GEMM: Y[M,N] = X[M,K] @ W[N,K]^T, cp.async double-buffered ---------
template <int MODE>
__global__ __launch_bounds__(256, 2)
void gemm_xwt(int xid,
              const float* __restrict__ Wr, const float* __restrict__ Wi,
              int yid, int K, int ldx, int ldw, int ldy,
              const float* __restrict__ br, const float* __restrict__ bi,
              int rid)
{
    const float* Xr = gbuf(xid, 0);
    const float* Xi = gbuf(xid, 1);
    float* Yr = gbuf(yid, 0);
    float* Yi = gbuf(yid, 1);

    __shared__ __align__(16) float As_r[2][BK][BPAD], As_i[2][BK][BPAD];
    __shared__ __align__(16) float Bs_r[2][BK][BPAD], Bs_i[2][BK][BPAD];

    int tid = threadIdx.x;
    int tx = tid & 15, ty = tid >> 4;
    int row0 = blockIdx.y*64, col0 = blockIdx.x*64;

    float cr[4][4] = {}, ci[4][4] = {};

    #define STAGE_G(buf, kt) { \
        _Pragma("unroll") \
        for (int i = 0; i < 4; i++) { \
            int r = ty + i*16, c = tx; \
            CPA4(scvt(&As_r[buf][c][r]), Xr + (size_t)(row0+r)*ldx + (kt) + c); \
            CPA4(scvt(&As_i[buf][c][r]), Xi + (size_t)(row0+r)*ldx + (kt) + c); \
            CPA4(scvt(&Bs_r[buf][c][r]), Wr + (size_t)(col0+r)*ldw + (kt) + c); \
            CPA4(scvt(&Bs_i[buf][c][r]), Wi + (size_t)(col0+r)*ldw + (kt) + c); \
        } }

    int nt = K / BK;
    STAGE_G(0, 0); CPCOMMIT();
    for (int it = 0; it < nt; it++) {
        int buf = it & 1;
        if (it+1 < nt) { STAGE_G(buf^1, (it+1)*BK); CPCOMMIT(); CPWAIT1(); }
        else           { CPWAIT0(); }
        __syncthreads();
        #pragma unroll
        for (int kk = 0; kk < BK; kk++) {
            float ar[4], ai_[4], br_[4], bi_[4];
            LOAD_FRAG(ar,  As_r[buf], kk, ty*4);
            LOAD_FRAG(ai_, As_i[buf], kk, ty*4);
            LOAD_FRAG(br_, Bs_r[buf], kk, tx*4);
            LOAD_FRAG(bi_, Bs_i[buf], kk, tx*4);
            #pragma unroll
            for (int i = 0; i < 4; i++)
                #pragma unroll
                for (int j = 0; j < 4; j++) {
                    cr[i][j] += ar[i]*br_[j] - ai_[i]*bi_[j];
                    ci[i][j] += ar[i]*bi_[j] + ai_[i]*br_[j];
                }
        }
        __syncthreads();
    }
    #undef STAGE_G

    const float* rr = gbuf(rid, 0);
    const float* ri = gbuf(rid, 1);
    int colb = col0 + tx*4;
    #pragma unroll
    for (int i = 0; i < 4; i++) {
        int row = row0 + ty*4 + i;
        size_t oi = (size_t)row*ldy + colb;
        float4 yr4, yi4;
        if (MODE == 0) {
            yr4 = make_float4(cr[i][0], cr[i][1], cr[i][2], cr[i][3]);
            yi4 = make_float4(ci[i][0], ci[i][1], ci[i][2], ci[i][3]);
        } else if (MODE == 1) {
            float4 b_r = *(const float4*)&br[colb];
            float4 b_i = *(const float4*)&bi[colb];
            float4 r_r = *(const float4*)&rr[oi];
            float4 r_i = *(const float4*)&ri[oi];
            yr4 = make_float4(cr[i][0]+b_r.x+r_r.x, cr[i][1]+b_r.y+r_r.y,
                              cr[i][2]+b_r.z+r_r.z, cr[i][3]+b_r.w+r_r.w);
            yi4 = make_float4(ci[i][0]+b_i.x+r_i.x, ci[i][1]+b_i.y+r_i.y,
                              ci[i][2]+b_i.z+r_i.z, ci[i][3]+b_i.w+r_i.w);
        } else {
            float4 r_r = *(const float4*)&rr[oi];
            float4 r_i = *(const float4*)&ri[oi];
            yr4 = make_float4(fmaxf(r_r.x + 0.1f*cr[i][0] - 0.01f, 0.f),
                              fmaxf(r_r.y + 0.1f*cr[i][1] - 0.01f, 0.f),
                              fmaxf(r_r.z + 0.1f*cr[i][2] - 0.01f, 0.f),
                              fmaxf(r_r.w + 0.1f*cr[i][3] - 0.01f, 0.f));
            yi4 = make_float4(fmaxf(r_i.x + 0.1f*ci[i][0], 0.f),
                              fmaxf(r_i.y + 0.1f*ci[i][1], 0.f),
                              fmaxf(r_i.z + 0.1f*ci[i][2], 0.f),
                              fmaxf(r_i.w + 0.1f*ci[i][3], 0.f));
        }
        *(float4*)&Yr[oi] = yr4;
        *(float4*)&Yi[oi] = yi4;
    }
}

// ---------------- dots: Hermitian upper-triangle, cp.async double-buffered ----------------
__global__ __launch_bounds__(256, 2)
void dots_kernel()
{
    int bh = blockIdx.y;
    int b = bh >> 2, h = bh & 3;
    const float* Ar = g_w_re + (size_t)b*SEQ*INNER + h*DH;
    const float* Ai = g_w_im + (size_t)b*SEQ*INNER + h*DH;

    int t = blockIdx.x, bi = 0;
    while (t >= 16 - bi) { t -= 16 - bi; bi++; }
    int bj = bi + t;
    int row0 = bi*64, col0 = bj*64;

    __shared__ __align__(16) float As_r[2][BK][BPAD], As_i[2][BK][BPAD];
    __shared__ __align__(16) float Bs_r[2][BK][BPAD], Bs_i[2][BK][BPAD];

    int tid = threadIdx.x;
    int tx = tid & 15, ty = tid >> 4;

    float cr[4][4] = {}, ci[4][4] = {};

    #define STAGE_D(buf, kt) { \
        _Pragma("unroll") \
        for (int i = 0; i < 4; i++) { \
            int r = ty + i*16, c = tx; \
            CPA4(scvt(&As_r[buf][c][r]), Ar + (size_t)(row0+r)*INNER + (kt) + c); \
            CPA4(scvt(&As_i[buf][c][r]), Ai + (size_t)(row0+r)*INNER + (kt) + c); \
            CPA4(scvt(&Bs_r[buf][c][r]), Ar + (size_t)(col0+r)*INNER + (kt) + c); \
            CPA4(scvt(&Bs_i[buf][c][r]), Ai + (size_t)(col0+r)*INNER + (kt) + c); \
        } }

    const int nt = DH / BK;   // 4
    STAGE_D(0, 0); CPCOMMIT();
    #pragma unroll
    for (int it = 0; it < nt; it++) {
        int buf = it & 1;
        if (it+1 < nt) { STAGE_D(buf^1, (it+1)*BK); CPCOMMIT(); CPWAIT1(); }
        else           { CPWAIT0(); }
        __syncthreads();
        #pragma unroll
        for (int kk = 0; kk < BK; kk++) {
            float qr[4], qi[4], kr[4], ki[4];
            LOAD_FRAG(qr, As_r[buf], kk, ty*4);
            LOAD_FRAG(qi, As_i[buf], kk, ty*4);
            LOAD_FRAG(kr, Bs_r[buf], kk, tx*4);
            LOAD_FRAG(ki, Bs_i[buf], kk, tx*4);
            #pragma unroll
            for (int i = 0; i < 4; i++)
                #pragma unroll
                for (int j = 0; j < 4; j++) {
                    cr[i][j] += qr[i]*kr[j] + qi[i]*ki[j];
                    ci[i][j] += qi[i]*kr[j] - qr[i]*ki[j];
                }
        }
        __syncthreads();
    }
    #undef STAGE_D

    const float SCALE = 0.125f;
    size_t obase = (size_t)bh*SEQ*SEQ;

    float ur[4][4], ui[4][4], mg[4][4];
    #pragma unroll
    for (int i = 0; i < 4; i++)
        #pragma unroll
        for (int j = 0; j < 4; j++) {
            float d2 = cr[i][j]*cr[i][j] + ci[i][j]*ci[i][j];
            float rs = rsqrtf(d2);
            bool  nz = d2 > 0.f;
            mg[i][j] = nz ? SCALE*d2*rs : 0.f;
            ur[i][j] = nz ? cr[i][j]*rs : 1.f;
            ui[i][j] = nz ? ci[i][j]*rs : 0.f;
        }

    int colb = col0 + tx*4;
    #pragma unroll
    for (int i = 0; i < 4; i++) {
        int row = row0 + ty*4 + i;
        size_t oi = obase + (size_t)row*SEQ + colb;
        *(float4*)&g_d_re[oi] = make_float4(ur[i][0], ur[i][1], ur[i][2], ur[i][3]);
        *(float4*)&g_d_im[oi] = make_float4(ui[i][0], ui[i][1], ui[i][2], ui[i][3]);
        *(float4*)&g_d_mg[oi] = make_float4(mg[i][0], mg[i][1], mg[i][2], mg[i][3]);
    }

    if (bi != bj) {
        int rowt = row0 + ty*4;
        #pragma unroll
        for (int j = 0; j < 4; j++) {
            int rt = colb + j;
            size_t oi = obase + (size_t)rt*SEQ + rowt;
            *(float4*)&g_d_re[oi] = make_float4( ur[0][j],  ur[1][j],  ur[2][j],  ur[3][j]);
            *(float4*)&g_d_im[oi] = make_float4(-ui[0][j], -ui[1][j], -ui[2][j], -ui[3][j]);
            *(float4*)&g_d_mg[oi] = make_float4( mg[0][j],  mg[1][j],  mg[2][j],  mg[3][j]);
        }
    }
}

// ---------------- softmax on stored magnitudes; scale unit phase in place ----------------
__global__ void softmax_polar()
{
    size_t base = (size_t)blockIdx.x * SEQ;
    int t = threadIdx.x;
    float mg[4];
    float lmax = -3.4e38f;
    #pragma unroll
    for (int j = 0; j < 4; j++) {
        mg[j] = g_d_mg[base + t + 256*j];
        lmax = fmaxf(lmax, mg[j]);
    }
    __shared__ float sw[8];
    float v = lmax;
    #pragma unroll
    for (int o = 16; o > 0; o >>= 1) v = fmaxf(v, __shfl_xor_sync(0xffffffffu, v, o));
    if ((t & 31) == 0) sw[t>>5] = v;
    __syncthreads();
    float bmax = fmaxf(fmaxf(fmaxf(sw[0],sw[1]),fmaxf(sw[2],sw[3])),
                       fmaxf(fmaxf(sw[4],sw[5]),fmaxf(sw[6],sw[7])));
    __syncthreads();

    float e[4]; float lsum = 0.f;
    #pragma unroll
    for (int j = 0; j < 4; j++) { e[j] = __expf(mg[j] - bmax); lsum += e[j]; }
    v = lsum;
    #pragma unroll
    for (int o = 16; o > 0; o >>= 1) v += __shfl_xor_sync(0xffffffffu, v, o);
    if ((t & 31) == 0) sw[t>>5] = v;
    __syncthreads();
    float bsum = sw[0]+sw[1]+sw[2]+sw[3]+sw[4]+sw[5]+sw[6]+sw[7];
    float inv = 1.0f / bsum;

    #pragma unroll
    for (int j = 0; j < 4; j++) {
        size_t idx = base + t + 256*j;
        float amp = e[j] * inv;
        g_d_re[idx] *= amp;
        g_d_im[idx] *= amp;
    }
}

// ---------------- AV: O = C @ V per bh, cp.async double-buffered, 32x64 tiles ----------------
__global__ __launch_bounds__(256, 2)
void av_kernel()
{
    int bh = blockIdx.y; int b = bh >> 2, h = bh & 3;
    const float* Cr = g_d_re + (size_t)bh*SEQ*SEQ;
    const float* Ci = g_d_im + (size_t)bh*SEQ*SEQ;
    const float* Vr = g_w_re + (size_t)b*SEQ*INNER + h*DH;
    const float* Vi = g_w_im + (size_t)b*SEQ*INNER + h*DH;

    __shared__ __align__(16) float As_r[2][BK][36], As_i[2][BK][36];
    __shared__ __align__(16) float Bs_r[2][BK][BPAD], Bs_i[2][BK][BPAD];

    int tid = threadIdx.x;
    int tx = tid & 15, ty = tid >> 4;
    int row0 = blockIdx.x*32;

    float cr[2][4] = {}, ci[2][4] = {};

    // A: 32 rows x 16 k, transposed (4B copies); B: 16 k-rows x 64 cols (16B copies)
    #define STAGE_A(buf, kt) { \
        _Pragma("unroll") \
        for (int i = 0; i < 2; i++) { \
            int r = ty + i*16, c = tx; \
            CPA4(scvt(&As_r[buf][c][r]), Cr + (size_t)(row0+r)*SEQ + (kt) + c); \
            CPA4(scvt(&As_i[buf][c][r]), Ci + (size_t)(row0+r)*SEQ + (kt) + c); \
        } \
        { int r = tid >> 4, c4 = (tid & 15)*4; \
          CPA16(scvt(&Bs_r[buf][r][c4]), Vr + (size_t)((kt)+r)*INNER + c4); \
          CPA16(scvt(&Bs_i[buf][r][c4]), Vi + (size_t)((kt)+r)*INNER + c4); } }

    int nt = SEQ / BK;   // 64
    STAGE_A(0, 0); CPCOMMIT();
    for (int it = 0; it < nt; it++) {
        int buf = it & 1;
        if (it+1 < nt) { STAGE_A(buf^1, (it+1)*BK); CPCOMMIT(); CPWAIT1(); }
        else           { CPWAIT0(); }
        __syncthreads();
        #pragma unroll
        for (int kk = 0; kk < BK; kk++) {
            float2 arf = *(const float2*)&As_r[buf][kk][ty*2];
            float2 aif = *(const float2*)&As_i[buf][kk][ty*2];
            float br_[4], bi_[4];
            LOAD_FRAG(br_, Bs_r[buf], kk, tx*4);
            LOAD_FRAG(bi_, Bs_i[buf], kk, tx*4);
            float ar[2]  = {arf.x, arf.y};
            float ai_[2] = {aif.x, aif.y};
            #pragma unroll
            for (int i = 0; i < 2; i++)
                #pragma unroll
                for (int j = 0; j < 4; j++) {
                    cr[i][j] += ar[i]*br_[j] - ai_[i]*bi_[j];
                    ci[i][j] += ar[i]*bi_[j] + ai_[i]*br_[j];
                }
        }
        __syncthreads();
    }
    #undef STAGE_A

    int colb = h*DH + tx*4;
    #pragma unroll
    for (int i = 0; i < 2; i++) {
        int row = row0 + ty*2 + i;
        size_t oi = (size_t)(b*SEQ + row)*INNER + colb;
        *(float4*)&g_att_re[oi] = make_float4(cr[i][0], cr[i][1], cr[i][2], cr[i][3]);
        *(float4*)&g_att_im[oi] = make_float4(ci[i][0], ci[i][1], ci[i][2], ci[i][3]);
    }
}

// ---------------- host launcher ----------------
extern "C" void kernel_launch(void* const* d_in, const int* in_sizes, int n_in,
                              void* d_out, int out_size)
{
    if (n_in < 18 || d_out == nullptr) return;

    int ix[2], nx = 0;
    int iw[6], nw = 0;
    int ip[10], np = 0;
    for (int i = 0; i < n_in; i++) {
        if      (in_sizes[i] == MTOK*DIMC        && nx < 2)  ix[nx++] = i;
        else if (in_sizes[i] == DEPTH*INNER*DIMC && nw < 6)  iw[nw++] = i;
        else if (in_sizes[i] == DEPTH*DIMC       && np < 10) ip[np++] = i;
    }
    if (nx != 2 || nw != 6 || np != 10) return;

    const float* x_re     = (const float*)d_in[ix[0]];
    const float* x_im     = (const float*)d_in[ix[1]];
    const float* qkv_re   = (const float*)d_in[iw[0]];
    const float* qkv_im   = (const float*)d_in[iw[1]];
    const float* out_w_re = (const float*)d_in[iw[2]];
    const float* out_w_im = (const float*)d_in[iw[3]];
    const float* ff_re    = (const float*)d_in[iw[4]];
    const float* ff_im    = (const float*)d_in[iw[5]];
    const float* ln1_w_re = (const float*)d_in[ip[0]];
    const float* ln1_w_im = (const float*)d_in[ip[1]];
    const float* ln1_b_re = (const float*)d_in[ip[2]];
    const float* ln1_b_im = (const float*)d_in[ip[3]];
    const float* out_b_re = (const float*)d_in[ip[4]];
    const float* out_b_im = (const float*)d_in[ip[5]];
    const float* ln2_w_re = (const float*)d_in[ip[6]];
    const float* ln2_w_im = (const float*)d_in[ip[7]];
    const float* ln2_b_re = (const float*)d_in[ip[8]];
    const float* ln2_b_im = (const float*)d_in[ip[9]];

    const int nTok = MTOK*DIMC;
    init_x_kernel<<<(nTok+255)/256, 256>>>(x_re, x_im, nTok);

    const int WSLICE = INNER*DIMC;
    for (int l = 0; l < DEPTH; l++) {
        ln_kernel<<<MTOK, 256>>>(0,
                                 ln1_w_re + l*DIMC, ln1_w_im + l*DIMC,
                                 ln1_b_re + l*DIMC, ln1_b_im + l*DIMC);
        gemm_xwt<0><<<dim3(INNER/64, MTOK/64), 256>>>(
            1, qkv_re + (size_t)l*WSLICE, qkv_im + (size_t)l*WSLICE,
            2, DIMC, DIMC, DIMC, INNER, nullptr, nullptr, 0);
        dots_kernel<<<dim3(136, BATCH*HEADS), 256>>>();
        softmax_polar<<<BATCH*HEADS*SEQ, 256>>>();
        av_kernel<<<dim3(SEQ/32, BATCH*HEADS), 256>>>();
        gemm_xwt<1><<<dim3(DIMC/64, MTOK/64), 256>>>(
            3, out_w_re + (size_t)l*WSLICE, out_w_im + (size_t)l*WSLICE,
            4, INNER, INNER, INNER, DIMC,
            out_b_re + l*DIMC, out_b_im + l*DIMC, 0);
        ln_kernel<<<MTOK, 256>>>(4,
                                 ln2_w_re + l*DIMC, ln2_w_im + l*DIMC,
                                 ln2_b_re + l*DIMC, ln2_b_im + l*DIMC);
        gemm_xwt<2><<<dim3(DIMC/64, MTOK/64), 256>>>(
            1, ff_re + (size_t)l*WSLICE, ff_im + (size_t)l*WSLICE,
            0, DIMC, DIMC, DIMC, DIMC,
            nullptr, nullptr, 1);
    }

    int nOut = nTok < out_size ? nTok : out_size;
    pack_out_kernel<<<(nOut+255)/256, 256>>>((float*)d_out, nOut);
}

// round 16
// speedup vs baseline: 1.1464x; 1.0275x over previous
#include <cuda_runtime.h>
#include <math.h>

#define BATCH 2
#define SEQ   1024
#define DIMC  256
#define HEADS 4
#define DH    64
#define INNER 256
#define MTOK  (BATCH*SEQ)   // 2048
#define DEPTH 4

#define ACT_CAP ((size_t)MTOK*DIMC)                 // 524288
#define SCR_CAP ((size_t)BATCH*HEADS*SEQ*SEQ)       // 8388608

#define BK 16
#define BPAD 68

// ---------------- cp.async helpers ----------------
__device__ __forceinline__ unsigned scvt(const void* p) {
    return (unsigned)__cvta_generic_to_shared(p);
}
#define CPA4(dst, src)  asm volatile("cp.async.ca.shared.global [%0], [%1], 4;"  :: "r"(dst), "l"(src) : "memory")
#define CPA16(dst, src) asm volatile("cp.async.ca.shared.global [%0], [%1], 16;" :: "r"(dst), "l"(src) : "memory")
#define CPCOMMIT() asm volatile("cp.async.commit_group;" ::: "memory")
#define CPWAIT0()  asm volatile("cp.async.wait_group 0;" ::: "memory")
#define CPWAIT1()  asm volatile("cp.async.wait_group 1;" ::: "memory")

// ---------------- scratch (device globals) ----------------
__device__ float g_x_re[ACT_CAP],  g_x_im[ACT_CAP];
__device__ float g_xn_re[ACT_CAP], g_xn_im[ACT_CAP];
__device__ float g_w_re[ACT_CAP],  g_w_im[ACT_CAP];
__device__ float g_att_re[ACT_CAP],g_att_im[ACT_CAP];
__device__ float g_gx_re[ACT_CAP], g_gx_im[ACT_CAP];
__device__ float g_p0_re[ACT_CAP], g_p0_im[ACT_CAP];   // av split-K partials
__device__ float g_p1_re[ACT_CAP], g_p1_im[ACT_CAP];
__device__ float g_d_re[SCR_CAP];   // unit phase re -> scaled coef re after softmax
__device__ float g_d_im[SCR_CAP];   // unit phase im -> scaled coef im after softmax
__device__ float g_d_mg[SCR_CAP];   // scaled magnitude

__device__ __forceinline__ float* gbuf(int id, int comp) {
    switch (id) {
        case 0: return comp ? g_x_im   : g_x_re;
        case 1: return comp ? g_xn_im  : g_xn_re;
        case 2: return comp ? g_w_im   : g_w_re;
        case 3: return comp ? g_att_im : g_att_re;
        default:return comp ? g_gx_im  : g_gx_re;
    }
}

// ---------------- input copy ----------------
__global__ void init_x_kernel(const float* __restrict__ a, const float* __restrict__ b, int n)
{
    int i = blockIdx.x*blockDim.x + threadIdx.x;
    if (i < n) { g_x_re[i] = a[i]; g_x_im[i] = b[i]; }
}

// ---------------- output pack: real part only ----------------
__global__ void pack_out_kernel(float* __restrict__ out, int n)
{
    int i = blockIdx.x*blockDim.x + threadIdx.x;
    if (i < n) out[i] = g_x_re[i];
}

// ---------------- complex layernorm ----------------
__global__ void ln_kernel(int srcid,
                          const float* __restrict__ wr, const float* __restrict__ wi,
                          const float* __restrict__ br, const float* __restrict__ bi)
{
    const float* xr = gbuf(srcid, 0);
    const float* xi = gbuf(srcid, 1);
    float* yr = gbuf(1, 0);
    float* yi = gbuf(1, 1);

    int tok = blockIdx.x;
    int t   = threadIdx.x;
    size_t xidx = (size_t)tok*DIMC + t;
    float vr = xr[xidx];
    float vi = xi[xidx];

    float s0 = vr, s1 = vi, s2 = vr*vr, s3 = vi*vi;
    #pragma unroll
    for (int o = 16; o > 0; o >>= 1) {
        s0 += __shfl_xor_sync(0xffffffffu, s0, o);
        s1 += __shfl_xor_sync(0xffffffffu, s1, o);
        s2 += __shfl_xor_sync(0xffffffffu, s2, o);
        s3 += __shfl_xor_sync(0xffffffffu, s3, o);
    }
    __shared__ float sh0[8], sh1[8], sh2[8], sh3[8];
    int warp = t >> 5;
    if ((t & 31) == 0) { sh0[warp]=s0; sh1[warp]=s1; sh2[warp]=s2; sh3[warp]=s3; }
    __syncthreads();
    float t0=0.f, t1=0.f, t2=0.f, t3=0.f;
    #pragma unroll
    for (int i = 0; i < 8; i++) { t0+=sh0[i]; t1+=sh1[i]; t2+=sh2[i]; t3+=sh3[i]; }

    const float inv = 1.0f / DIMC;
    float mr = t0*inv, mi = t1*inv;
    float var_r = t2*inv - mr*mr;
    float var_i = t3*inv - mi*mi;
    float a = var_r + 1e-5f, b = var_i;
    float r = sqrtf(a*a + b*b);
    float sre = sqrtf(fmaxf(0.5f*(r + a), 0.f));
    float sim = sqrtf(fmaxf(0.5f*(r - a), 0.f));
    if (b < 0.f) sim = -sim;
    float invr = 1.0f / fmaxf(r, 1e-30f);
    float dxr = vr - mr, dxi = vi - mi;
    float xnr = (dxr*sre + dxi*sim) * invr;
    float xni = (dxi*sre - dxr*sim) * invr;
    float Wr = wr[t], Wi = wi[t];
    yr[xidx] = Wr*xnr - Wi*xni + br[t];
    yi[xidx] = Wr*xni + Wi*xnr + bi[t];
}

#define LOAD_FRAG(dst, arr, kk, off)  { float4 _f = *(const float4*)&arr[kk][off]; \
                                        dst[0]=_f.x; dst[1]=_f.y; dst[2]=_f.z; dst[3]=_f.w; }

// ---------------- complex GEMM: Y[M,N] = X[M,K] @ W[N,K]^T, cp.async double-buffered ---------
template <int MODE>
__global__ __launch_bounds__(256, 2)
void gemm_xwt(int xid,
              const float* __restrict__ Wr, const float* __restrict__ Wi,
              int yid, int K, int ldx, int ldw, int ldy,
              const float* __restrict__ br, const float* __restrict__ bi,
              int rid)
{
    const float* Xr = gbuf(xid, 0);
    const float* Xi = gbuf(xid, 1);
    float* Yr = gbuf(yid, 0);
    float* Yi = gbuf(yid, 1);

    __shared__ __align__(16) float As_r[2][BK][BPAD], As_i[2][BK][BPAD];
    __shared__ __align__(16) float Bs_r[2][BK][BPAD], Bs_i[2][BK][BPAD];

    int tid = threadIdx.x;
    int tx = tid & 15, ty = tid >> 4;
    int row0 = blockIdx.y*64, col0 = blockIdx.x*64;

    float cr[4][4] = {}, ci[4][4] = {};

    #define STAGE_G(buf, kt) { \
        _Pragma("unroll") \
        for (int i = 0; i < 4; i++) { \
            int r = ty + i*16, c = tx; \
            CPA4(scvt(&As_r[buf][c][r]), Xr + (size_t)(row0+r)*ldx + (kt) + c); \
            CPA4(scvt(&As_i[buf][c][r]), Xi + (size_t)(row0+r)*ldx + (kt) + c); \
            CPA4(scvt(&Bs_r[buf][c][r]), Wr + (size_t)(col0+r)*ldw + (kt) + c); \
            CPA4(scvt(&Bs_i[buf][c][r]), Wi + (size_t)(col0+r)*ldw + (kt) + c); \
        } }

    int nt = K / BK;
    STAGE_G(0, 0); CPCOMMIT();
    for (int it = 0; it < nt; it++) {
        int buf = it & 1;
        if (it+1 < nt) { STAGE_G(buf^1, (it+1)*BK); CPCOMMIT(); CPWAIT1(); }
        else           { CPWAIT0(); }
        __syncthreads();
        #pragma unroll
        for (int kk = 0; kk < BK; kk++) {
            float ar[4], ai_[4], br_[4], bi_[4];
            LOAD_FRAG(ar,  As_r[buf], kk, ty*4);
            LOAD_FRAG(ai_, As_i[buf], kk, ty*4);
            LOAD_FRAG(br_, Bs_r[buf], kk, tx*4);
            LOAD_FRAG(bi_, Bs_i[buf], kk, tx*4);
            #pragma unroll
            for (int i = 0; i < 4; i++)
                #pragma unroll
                for (int j = 0; j < 4; j++) {
                    cr[i][j] += ar[i]*br_[j] - ai_[i]*bi_[j];
                    ci[i][j] += ar[i]*bi_[j] + ai_[i]*br_[j];
                }
        }
        __syncthreads();
    }
    #undef STAGE_G

    const float* rr = gbuf(rid, 0);
    const float* ri = gbuf(rid, 1);
    int colb = col0 + tx*4;
    #pragma unroll
    for (int i = 0; i < 4; i++) {
        int row = row0 + ty*4 + i;
        size_t oi = (size_t)row*ldy + colb;
        float4 yr4, yi4;
        if (MODE == 0) {
            yr4 = make_float4(cr[i][0], cr[i][1], cr[i][2], cr[i][3]);
            yi4 = make_float4(ci[i][0], ci[i][1], ci[i][2], ci[i][3]);
        } else if (MODE == 1) {
            float4 b_r = *(const float4*)&br[colb];
            float4 b_i = *(const float4*)&bi[colb];
            float4 r_r = *(const float4*)&rr[oi];
            float4 r_i = *(const float4*)&ri[oi];
            yr4 = make_float4(cr[i][0]+b_r.x+r_r.x, cr[i][1]+b_r.y+r_r.y,
                              cr[i][2]+b_r.z+r_r.z, cr[i][3]+b_r.w+r_r.w);
            yi4 = make_float4(ci[i][0]+b_i.x+r_i.x, ci[i][1]+b_i.y+r_i.y,
                              ci[i][2]+b_i.z+r_i.z, ci[i][3]+b_i.w+r_i.w);
        } else {
            float4 r_r = *(const float4*)&rr[oi];
            float4 r_i = *(const float4*)&ri[oi];
            yr4 = make_float4(fmaxf(r_r.x + 0.1f*cr[i][0] - 0.01f, 0.f),
                              fmaxf(r_r.y + 0.1f*cr[i][1] - 0.01f, 0.f),
                              fmaxf(r_r.z + 0.1f*cr[i][2] - 0.01f, 0.f),
                              fmaxf(r_r.w + 0.1f*cr[i][3] - 0.01f, 0.f));
            yi4 = make_float4(fmaxf(r_i.x + 0.1f*ci[i][0], 0.f),
                              fmaxf(r_i.y + 0.1f*ci[i][1], 0.f),
                              fmaxf(r_i.z + 0.1f*ci[i][2], 0.f),
                              fmaxf(r_i.w + 0.1f*ci[i][3], 0.f));
        }
        *(float4*)&Yr[oi] = yr4;
        *(float4*)&Yi[oi] = yi4;
    }
}

// ---------------- dots: Hermitian upper-triangle, cp.async double-buffered ----------------
__global__ __launch_bounds__(256, 2)
void dots_kernel()
{
    int bh = blockIdx.y;
    int b = bh >> 2, h = bh & 3;
    const float* Ar = g_w_re + (size_t)b*SEQ*INNER + h*DH;
    const float* Ai = g_w_im + (size_t)b*SEQ*INNER + h*DH;

    int t = blockIdx.x, bi = 0;
    while (t >= 16 - bi) { t -= 16 - bi; bi++; }
    int bj = bi + t;
    int row0 = bi*64, col0 = bj*64;

    __shared__ __align__(16) float As_r[2][BK][BPAD], As_i[2][BK][BPAD];
    __shared__ __align__(16) float Bs_r[2][BK][BPAD], Bs_i[2][BK][BPAD];

    int tid = threadIdx.x;
    int tx = tid & 15, ty = tid >> 4;

    float cr[4][4] = {}, ci[4][4] = {};

    #define STAGE_D(buf, kt) { \
        _Pragma("unroll") \
        for (int i = 0; i < 4; i++) { \
            int r = ty + i*16, c = tx; \
            CPA4(scvt(&As_r[buf][c][r]), Ar + (size_t)(row0+r)*INNER + (kt) + c); \
            CPA4(scvt(&As_i[buf][c][r]), Ai + (size_t)(row0+r)*INNER + (kt) + c); \
            CPA4(scvt(&Bs_r[buf][c][r]), Ar + (size_t)(col0+r)*INNER + (kt) + c); \
            CPA4(scvt(&Bs_i[buf][c][r]), Ai + (size_t)(col0+r)*INNER + (kt) + c); \
        } }

    const int nt = DH / BK;   // 4
    STAGE_D(0, 0); CPCOMMIT();
    #pragma unroll
    for (int it = 0; it < nt; it++) {
        int buf = it & 1;
        if (it+1 < nt) { STAGE_D(buf^1, (it+1)*BK); CPCOMMIT(); CPWAIT1(); }
        else           { CPWAIT0(); }
        __syncthreads();
        #pragma unroll
        for (int kk = 0; kk < BK; kk++) {
            float qr[4], qi[4], kr[4], ki[4];
            LOAD_FRAG(qr, As_r[buf], kk, ty*4);
            LOAD_FRAG(qi, As_i[buf], kk, ty*4);
            LOAD_FRAG(kr, Bs_r[buf], kk, tx*4);
            LOAD_FRAG(ki, Bs_i[buf], kk, tx*4);
            #pragma unroll
            for (int i = 0; i < 4; i++)
                #pragma unroll
                for (int j = 0; j < 4; j++) {
                    cr[i][j] += qr[i]*kr[j] + qi[i]*ki[j];
                    ci[i][j] += qi[i]*kr[j] - qr[i]*ki[j];
                }
        }
        __syncthreads();
    }
    #undef STAGE_D

    const float SCALE = 0.125f;
    size_t obase = (size_t)bh*SEQ*SEQ;

    float ur[4][4], ui[4][4], mg[4][4];
    #pragma unroll
    for (int i = 0; i < 4; i++)
        #pragma unroll
        for (int j = 0; j < 4; j++) {
            float d2 = cr[i][j]*cr[i][j] + ci[i][j]*ci[i][j];
            float rs = rsqrtf(d2);
            bool  nz = d2 > 0.f;
            mg[i][j] = nz ? SCALE*d2*rs : 0.f;
            ur[i][j] = nz ? cr[i][j]*rs : 1.f;
            ui[i][j] = nz ? ci[i][j]*rs : 0.f;
        }

    int colb = col0 + tx*4;
    #pragma unroll
    for (int i = 0; i < 4; i++) {
        int row = row0 + ty*4 + i;
        size_t oi = obase + (size_t)row*SEQ + colb;
        *(float4*)&g_d_re[oi] = make_float4(ur[i][0], ur[i][1], ur[i][2], ur[i][3]);
        *(float4*)&g_d_im[oi] = make_float4(ui[i][0], ui[i][1], ui[i][2], ui[i][3]);
        *(float4*)&g_d_mg[oi] = make_float4(mg[i][0], mg[i][1], mg[i][2], mg[i][3]);
    }

    if (bi != bj) {
        int rowt = row0 + ty*4;
        #pragma unroll
        for (int j = 0; j < 4; j++) {
            int rt = colb + j;
            size_t oi = obase + (size_t)rt*SEQ + rowt;
            *(float4*)&g_d_re[oi] = make_float4( ur[0][j],  ur[1][j],  ur[2][j],  ur[3][j]);
            *(float4*)&g_d_im[oi] = make_float4(-ui[0][j], -ui[1][j], -ui[2][j], -ui[3][j]);
            *(float4*)&g_d_mg[oi] = make_float4( mg[0][j],  mg[1][j],  mg[2][j],  mg[3][j]);
        }
    }
}

// ---------------- softmax on stored magnitudes; scale unit phase in place ----------------
__global__ void softmax_polar()
{
    size_t base = (size_t)blockIdx.x * SEQ;
    int t = threadIdx.x;
    float mg[4];
    float lmax = -3.4e38f;
    #pragma unroll
    for (int j = 0; j < 4; j++) {
        mg[j] = g_d_mg[base + t + 256*j];
        lmax = fmaxf(lmax, mg[j]);
    }
    __shared__ float sw[8];
    float v = lmax;
    #pragma unroll
    for (int o = 16; o > 0; o >>= 1) v = fmaxf(v, __shfl_xor_sync(0xffffffffu, v, o));
    if ((t & 31) == 0) sw[t>>5] = v;
    __syncthreads();
    float bmax = fmaxf(fmaxf(fmaxf(sw[0],sw[1]),fmaxf(sw[2],sw[3])),
                       fmaxf(fmaxf(sw[4],sw[5]),fmaxf(sw[6],sw[7])));
    __syncthreads();

    float e[4]; float lsum = 0.f;
    #pragma unroll
    for (int j = 0; j < 4; j++) { e[j] = __expf(mg[j] - bmax); lsum += e[j]; }
    v = lsum;
    #pragma unroll
    for (int o = 16; o > 0; o >>= 1) v += __shfl_xor_sync(0xffffffffu, v, o);
    if ((t & 31) == 0) sw[t>>5] = v;
    __syncthreads();
    float bsum = sw[0]+sw[1]+sw[2]+sw[3]+sw[4]+sw[5]+sw[6]+sw[7];
    float inv = 1.0f / bsum;

    #pragma unroll
    for (int j = 0; j < 4; j++) {
        size_t idx = base + t + 256*j;
        float amp = e[j] * inv;
        g_d_re[idx] *= amp;
        g_d_im[idx] *= amp;
    }
}

// ---------------- AV split-K: 64x64 tile, 4x4 microtile, K=512 per z ----------------
// grid (SEQ/64, BATCH*HEADS, 2)
__global__ __launch_bounds__(256, 2)
void av_kernel()
{
    int bh = blockIdx.y; int b = bh >> 2, h = bh & 3;
    int zk = blockIdx.z;
    const float* Cr = g_d_re + (size_t)bh*SEQ*SEQ;
    const float* Ci = g_d_im + (size_t)bh*SEQ*SEQ;
    const float* Vr = g_w_re + (size_t)b*SEQ*INNER + h*DH;
    const float* Vi = g_w_im + (size_t)b*SEQ*INNER + h*DH;
    float* Pr = zk ? g_p1_re : g_p0_re;
    float* Pi = zk ? g_p1_im : g_p0_im;

    __shared__ __align__(16) float As_r[2][BK][BPAD], As_i[2][BK][BPAD];
    __shared__ __align__(16) float Bs_r[2][BK][BPAD], Bs_i[2][BK][BPAD];

    int tid = threadIdx.x;
    int tx = tid & 15, ty = tid >> 4;
    int row0 = blockIdx.x*64;
    int kbase = zk*(SEQ/2);

    float cr[4][4] = {}, ci[4][4] = {};

    // A: scores 64 rows x 16 k transposed (4B); B: V 16 k-rows x 64 cols (16B)
    #define STAGE_A(buf, kt) { \
        _Pragma("unroll") \
        for (int i = 0; i < 4; i++) { \
            int r = ty + i*16, c = tx; \
            CPA4(scvt(&As_r[buf][c][r]), Cr + (size_t)(row0+r)*SEQ + (kt) + c); \
            CPA4(scvt(&As_i[buf][c][r]), Ci + (size_t)(row0+r)*SEQ + (kt) + c); \
        } \
        { int r = tid >> 4, c4 = (tid & 15)*4; \
          CPA16(scvt(&Bs_r[buf][r][c4]), Vr + (size_t)((kt)+r)*INNER + c4); \
          CPA16(scvt(&Bs_i[buf][r][c4]), Vi + (size_t)((kt)+r)*INNER + c4); } }

    const int nt = (SEQ/2) / BK;   // 32
    STAGE_A(0, kbase); CPCOMMIT();
    for (int it = 0; it < nt; it++) {
        int buf = it & 1;
        if (it+1 < nt) { STAGE_A(buf^1, kbase + (it+1)*BK); CPCOMMIT(); CPWAIT1(); }
        else           { CPWAIT0(); }
        __syncthreads();
        #pragma unroll
        for (int kk = 0; kk < BK; kk++) {
            float ar[4], ai_[4], br_[4], bi_[4];
            LOAD_FRAG(ar,  As_r[buf], kk, ty*4);
            LOAD_FRAG(ai_, As_i[buf], kk, ty*4);
            LOAD_FRAG(br_, Bs_r[buf], kk, tx*4);
            LOAD_FRAG(bi_, Bs_i[buf], kk, tx*4);
            #pragma unroll
            for (int i = 0; i < 4; i++)
                #pragma unroll
                for (int j = 0; j < 4; j++) {
                    cr[i][j] += ar[i]*br_[j] - ai_[i]*bi_[j];
                    ci[i][j] += ar[i]*bi_[j] + ai_[i]*br_[j];
                }
        }
        __syncthreads();
    }
    #undef STAGE_A

    int colb = h*DH + tx*4;
    #pragma unroll
    for (int i = 0; i < 4; i++) {
        int row = row0 + ty*4 + i;
        size_t oi = (size_t)(b*SEQ + row)*INNER + colb;
        *(float4*)&Pr[oi] = make_float4(cr[i][0], cr[i][1], cr[i][2], cr[i][3]);
        *(float4*)&Pi[oi] = make_float4(ci[i][0], ci[i][1], ci[i][2], ci[i][3]);
    }
}

// ---------------- av reduce: att = p0 + p1 (vectorized) ----------------
__global__ void av_reduce_kernel()
{
    int i = blockIdx.x*blockDim.x + threadIdx.x;   // float4 index
    if (i < (int)(ACT_CAP/4)) {
        float4 a = ((const float4*)g_p0_re)[i];
        float4 b = ((const float4*)g_p1_re)[i];
        ((float4*)g_att_re)[i] = make_float4(a.x+b.x, a.y+b.y, a.z+b.z, a.w+b.w);
        float4 c = ((const float4*)g_p0_im)[i];
        float4 d = ((const float4*)g_p1_im)[i];
        ((float4*)g_att_im)[i] = make_float4(c.x+d.x, c.y+d.y, c.z+d.z, c.w+d.w);
    }
}

// ---------------- host launcher ----------------
extern "C" void kernel_launch(void* const* d_in, const int* in_sizes, int n_in,
                              void* d_out, int out_size)
{
    if (n_in < 18 || d_out == nullptr) return;

    int ix[2], nx = 0;
    int iw[6], nw = 0;
    int ip[10], np = 0;
    for (int i = 0; i < n_in; i++) {
        if      (in_sizes[i] == MTOK*DIMC        && nx < 2)  ix[nx++] = i;
        else if (in_sizes[i] == DEPTH*INNER*DIMC && nw < 6)  iw[nw++] = i;
        else if (in_sizes[i] == DEPTH*DIMC       && np < 10) ip[np++] = i;
    }
    if (nx != 2 || nw != 6 || np != 10) return;

    const float* x_re     = (const float*)d_in[ix[0]];
    const float* x_im     = (const float*)d_in[ix[1]];
    const float* qkv_re   = (const float*)d_in[iw[0]];
    const float* qkv_im   = (const float*)d_in[iw[1]];
    const float* out_w_re = (const float*)d_in[iw[2]];
    const float* out_w_im = (const float*)d_in[iw[3]];
    const float* ff_re    = (const float*)d_in[iw[4]];
    const float* ff_im    = (const float*)d_in[iw[5]];
    const float* ln1_w_re = (const float*)d_in[ip[0]];
    const float* ln1_w_im = (const float*)d_in[ip[1]];
    const float* ln1_b_re = (const float*)d_in[ip[2]];
    const float* ln1_b_im = (const float*)d_in[ip[3]];
    const float* out_b_re = (const float*)d_in[ip[4]];
    const float* out_b_im = (const float*)d_in[ip[5]];
    const float* ln2_w_re = (const float*)d_in[ip[6]];
    const float* ln2_w_im = (const float*)d_in[ip[7]];
    const float* ln2_b_re = (const float*)d_in[ip[8]];
    const float* ln2_b_im = (const float*)d_in[ip[9]];

    const int nTok = MTOK*DIMC;
    init_x_kernel<<<(nTok+255)/256, 256>>>(x_re, x_im, nTok);

    const int WSLICE = INNER*DIMC;
    for (int l = 0; l < DEPTH; l++) {
        ln_kernel<<<MTOK, 256>>>(0,
                                 ln1_w_re + l*DIMC, ln1_w_im + l*DIMC,
                                 ln1_b_re + l*DIMC, ln1_b_im + l*DIMC);
        gemm_xwt<0><<<dim3(INNER/64, MTOK/64), 256>>>(
            1, qkv_re + (size_t)l*WSLICE, qkv_im + (size_t)l*WSLICE,
            2, DIMC, DIMC, DIMC, INNER, nullptr, nullptr, 0);
        dots_kernel<<<dim3(136, BATCH*HEADS), 256>>>();
        softmax_polar<<<BATCH*HEADS*SEQ, 256>>>();
        av_kernel<<<dim3(SEQ/64, BATCH*HEADS, 2), 256>>>();
        av_reduce_kernel<<<(ACT_CAP/4 + 255)/256, 256>>>();
        gemm_xwt<1><<<dim3(DIMC/64, MTOK/64), 256>>>(
            3, out_w_re + (size_t)l*WSLICE, out_w_im + (size_t)l*WSLICE,
            4, INNER, INNER, INNER, DIMC,
            out_b_re + l*DIMC, out_b_im + l*DIMC, 0);
        ln_kernel<<<MTOK, 256>>>(4,
                                 ln2_w_re + l*DIMC, ln2_w_im + l*DIMC,
                                 ln2_b_re + l*DIMC, ln2_b_im + l*DIMC);
        gemm_xwt<2><<<dim3(DIMC/64, MTOK/64), 256>>>(
            1, ff_re + (size_t)l*WSLICE, ff_im + (size_t)l*WSLICE,
            0, DIMC, DIMC, DIMC, DIMC,
            nullptr, nullptr, 1);
    }

    int nOut = nTok < out_size ? nTok : out_size;
    pack_out_kernel<<<(nOut+255)/256, 256>>>((float*)d_out, nOut);
}